// round 14
// baseline (speedup 1.0000x reference)
#include <cuda_runtime.h>
#include <cuda_fp16.h>
#include <cstdint>
#include <math.h>
#include <mma.h>

using namespace nvcuda;

// Problem constants
#define BB 2
#define SS 2048
#define HH 12
#define DHD 64
#define DD 768
#define DFF 3072
#define MM (BB*SS)
#define Y_ELEMS ((size_t)BB*SS*DD)

// ---------------- scratch (device globals) ---------------------------------
__device__ float g_ao[BB*SS*DD];
__device__ float g_h [BB*SS*DD];
__device__ float g_f2[BB*SS*DD];

// fp16 buffers
__device__ __half g_qh [BB*HH*SS*DHD];
__device__ __half g_kh [BB*HH*SS*DHD];
__device__ __half g_vh [BB*HH*SS*DHD];
__device__ __half g_xh [BB*SS*DD];
__device__ __half g_wqh[DD*DD];
__device__ __half g_wkh[DD*DD];
__device__ __half g_wvh[DD*DD];
__device__ __half g_woh[DD*DD];
__device__ __half g_w1h[DFF*DD];
__device__ __half g_w2h[DD*DFF];
__device__ __half g_avh[BB*SS*DD];
__device__ __half g_hh [BB*SS*DD];
__device__ __half g_f1h[BB*SS*DFF];

__device__ __forceinline__ void cp_async16(unsigned int dst, const void* src) {
    asm volatile("cp.async.cg.shared.global [%0], [%1], 16;\n" :: "r"(dst), "l"(src));
}
__device__ __forceinline__ void cp_commit() {
    asm volatile("cp.async.commit_group;\n");
}
__device__ __forceinline__ void cp_wait0() {
    asm volatile("cp.async.wait_group 0;\n");
}
__device__ __forceinline__ void cp_wait1() {
    asm volatile("cp.async.wait_group 1;\n");
}

// FMA-pipe exp of (x * 1/8)
__device__ __forceinline__ float fexp8(float x) {
    float t  = fmaxf(x * 0.18033688011112042f, -115.0f);
    float fi = rintf(t);
    float f  = t - fi;
    float p  = 1.3393036e-3f;
    p = fmaf(p, f, 9.6181316e-3f);
    p = fmaf(p, f, 5.5504109e-2f);
    p = fmaf(p, f, 2.4022651e-1f);
    p = fmaf(p, f, 6.9314718e-1f);
    p = fmaf(p, f, 1.0f);
    return __int_as_float(__float_as_int(p) + ((int)fi << 23));
}

// ---------------- fp32 -> fp16 convert -------------------------------------
__global__ void f2h(const float* __restrict__ in, __half* __restrict__ out)
{
    const size_t i = ((size_t)blockIdx.x * 256 + threadIdx.x) * 4;
    float4 v = *(const float4*)&in[i];
    *(__half2*)&out[i]     = __floats2half2_rn(v.x, v.y);
    *(__half2*)&out[i + 2] = __floats2half2_rn(v.z, v.w);
}

// ====  fp16 NT GEMM: 256x128 CTA tile, 64x64 warp tile, 3-stage cp.async ===
#define HLD 72
#define ABUF (256*HLD)                       // A halfs per stage
#define BBUF (128*HLD)                       // B halfs per stage
#define GSTG 3
#define GEMMH_SMEM_BYTES (GSTG*(ABUF+BBUF)*2)   // 165,888 B

// MODE 0: fp32 C. MODE 2: bias+GELU -> half C. MODE 4: head-split half C.
template<int MODE>
__device__ __forceinline__ void gemm_h_body(const __half* __restrict__ A,
                                            const __half* __restrict__ B,
                                            const float* __restrict__ bias,
                                            void* __restrict__ Cv,
                                            int N, int K, int m0, int n0)
{
    extern __shared__ float gsm[];
    __half* As = (__half*)gsm;               // [GSTG][256][72]
    __half* Bs = As + GSTG*ABUF;             // [GSTG][128][72]

    const int tid  = threadIdx.x;            // 256
    const int warp = tid >> 5;               // 0..7
    const int wm   = warp & 3;               // 4 m-groups of 64
    const int wn   = warp >> 2;              // 2 n-groups of 64

    const unsigned int as_s = (unsigned int)__cvta_generic_to_shared(As);
    const unsigned int bs_s = (unsigned int)__cvta_generic_to_shared(Bs);

    wmma::fragment<wmma::accumulator, 16, 16, 16, float> c[4][4];
    #pragma unroll
    for (int i = 0; i < 4; i++)
        #pragma unroll
        for (int j = 0; j < 4; j++)
            wmma::fill_fragment(c[i][j], 0.0f);

    const int T = K >> 6;

    auto issue = [&](int t) {
        const int k0 = t << 6;
        const int stg = t % GSTG;
        const unsigned int aoff = (unsigned int)(stg * ABUF * 2);
        const unsigned int boff = (unsigned int)(stg * BBUF * 2);
        #pragma unroll
        for (int i = 0; i < 8; i++) {        // A: 2048 chunks
            int ch   = tid + i * 256;
            int row  = ch >> 3;
            int col8 = (ch & 7) * 8;
            cp_async16(as_s + aoff + (unsigned int)((row * HLD + col8) * 2),
                       &A[(size_t)(m0 + row) * K + k0 + col8]);
        }
        #pragma unroll
        for (int i = 0; i < 4; i++) {        // B: 1024 chunks
            int ch   = tid + i * 256;
            int row  = ch >> 3;
            int col8 = (ch & 7) * 8;
            cp_async16(bs_s + boff + (unsigned int)((row * HLD + col8) * 2),
                       &B[(size_t)(n0 + row) * K + k0 + col8]);
        }
        cp_commit();
    };

    issue(0);
    if (T > 1) issue(1);

    for (int t = 0; t < T; t++) {
        if (t + 1 < T) cp_wait1(); else cp_wait0();
        __syncthreads();
        if (t + 2 < T) issue(t + 2);

        const int astg = (t % GSTG) * ABUF;
        const int bstg = (t % GSTG) * BBUF;
        #pragma unroll
        for (int kk = 0; kk < 64; kk += 16) {
            wmma::fragment<wmma::matrix_a, 16, 16, 16, __half, wmma::row_major> a[4];
            wmma::fragment<wmma::matrix_b, 16, 16, 16, __half, wmma::col_major> b[4];
            #pragma unroll
            for (int i = 0; i < 4; i++)
                wmma::load_matrix_sync(a[i], &As[astg + (wm * 64 + i * 16) * HLD + kk], HLD);
            #pragma unroll
            for (int j = 0; j < 4; j++)
                wmma::load_matrix_sync(b[j], &Bs[bstg + (wn * 64 + j * 16) * HLD + kk], HLD);
            #pragma unroll
            for (int i = 0; i < 4; i++)
                #pragma unroll
                for (int j = 0; j < 4; j++)
                    wmma::mma_sync(c[i][j], a[i], b[j], c[i][j]);
        }
        __syncthreads();
    }

    if (MODE == 2 || MODE == 4) {
        // stage fp32 result [256][132] in smem, then epilogue per row
        float* stg = gsm;
        #pragma unroll
        for (int i = 0; i < 4; i++)
            #pragma unroll
            for (int j = 0; j < 4; j++)
                wmma::store_matrix_sync(&stg[(wm * 64 + i * 16) * 132 + wn * 64 + j * 16],
                                        c[i][j], 132, wmma::mem_row_major);
        __syncthreads();
        __half* C = (__half*)Cv;
        const int r = tid;                   // one row per thread (256 rows)
        if (MODE == 2) {
            #pragma unroll
            for (int cc = 0; cc < 128; cc += 4) {
                float4 v = *(float4*)&stg[r * 132 + cc];
                float4 bb = *(const float4*)&bias[n0 + cc];
                v.x += bb.x; v.y += bb.y; v.z += bb.z; v.w += bb.w;
                v.x = 0.5f * v.x * (1.0f + erff(v.x * 0.70710678118654752f));
                v.y = 0.5f * v.y * (1.0f + erff(v.y * 0.70710678118654752f));
                v.z = 0.5f * v.z * (1.0f + erff(v.z * 0.70710678118654752f));
                v.w = 0.5f * v.w * (1.0f + erff(v.w * 0.70710678118654752f));
                __half* dst = &C[(size_t)(m0 + r) * N + n0 + cc];
                *(__half2*)&dst[0] = __floats2half2_rn(v.x, v.y);
                *(__half2*)&dst[2] = __floats2half2_rn(v.z, v.w);
            }
        } else {
            int m = m0 + r;
            int bidx = m >> 11, s = m & 2047;
            #pragma unroll
            for (int seg = 0; seg < 2; seg++) {
                int h = (n0 + seg * 64) >> 6;
                __half* dst = &C[(((size_t)(bidx * HH + h)) * SS + s) * DHD];
                #pragma unroll
                for (int cc = 0; cc < 64; cc += 4) {
                    float4 v = *(float4*)&stg[r * 132 + seg * 64 + cc];
                    *(__half2*)&dst[cc]     = __floats2half2_rn(v.x, v.y);
                    *(__half2*)&dst[cc + 2] = __floats2half2_rn(v.z, v.w);
                }
            }
        }
    } else {
        float* C = (float*)Cv;
        #pragma unroll
        for (int i = 0; i < 4; i++) {
            int m = m0 + wm * 64 + i * 16;
            #pragma unroll
            for (int j = 0; j < 4; j++) {
                int n = n0 + wn * 64 + j * 16;
                wmma::store_matrix_sync(C + (size_t)m * N + n, c[i][j], N, wmma::mem_row_major);
            }
        }
    }
}

__global__ void __launch_bounds__(256)
gemm_h(const __half* __restrict__ A, const __half* __restrict__ B,
       float* __restrict__ C, int N, int K)
{
    gemm_h_body<0>(A, B, nullptr, C, N, K, blockIdx.y * 256, blockIdx.x * 128);
}

__global__ void __launch_bounds__(256)
gemm_h_gelu(const __half* __restrict__ A, const __half* __restrict__ B,
            const float* __restrict__ bias, __half* __restrict__ C, int N, int K)
{
    gemm_h_body<2>(A, B, bias, C, N, K, blockIdx.y * 256, blockIdx.x * 128);
}

__global__ void __launch_bounds__(256)
qkv_gemm_h(const __half* __restrict__ X,
           const __half* __restrict__ Wq, const __half* __restrict__ Wk,
           const __half* __restrict__ Wv,
           __half* __restrict__ Qo, __half* __restrict__ Ko, __half* __restrict__ Vo)
{
    const __half* B = (blockIdx.z == 0) ? Wq : (blockIdx.z == 1) ? Wk : Wv;
    __half*       C = (blockIdx.z == 0) ? Qo : (blockIdx.z == 1) ? Ko : Vo;
    gemm_h_body<4>(X, B, nullptr, C, DD, DD, blockIdx.y * 256, blockIdx.x * 128);
}

// ==============  fused flash attention, fp16 MMA, cp.async  ================
#define AT_QH 0
#define AT_KH 18432
#define AT_VH 36864
#define AT_SS 73728
#define AT_ES 141312
#define AT_LS 176128
#define ATT_SMEM_BYTES 176640
#define HLDA 72
#define HBUFA (128*HLDA)

__global__ void __launch_bounds__(512, 1)
attn_fused(const __half* __restrict__ Q, const __half* __restrict__ K,
           const __half* __restrict__ V, float* __restrict__ P,
           __half* __restrict__ AVh)
{
    extern __shared__ char smraw[];
    __half* Qh = (__half*)(smraw + AT_QH);
    __half* Kh = (__half*)(smraw + AT_KH);
    __half* Vh = (__half*)(smraw + AT_VH);
    float*  Ss = (float*)(smraw + AT_SS);
    __half* Es = (__half*)(smraw + AT_ES);
    float*  ls = (float*)(smraw + AT_LS);

    const int bh  = blockIdx.y;
    const int qt  = gridDim.x - 1 - blockIdx.x;
    const int m0  = qt * 128;
    const int tid = threadIdx.x;
    const int warp = tid >> 5;
    const int wm = warp & 3;
    const int wn = warp >> 2;

    const __half* Qb = Q + ((size_t)bh * SS + m0) * DHD;
    const __half* Kb = K + (size_t)bh * SS * DHD;
    const __half* Vb = V + (size_t)bh * SS * DHD;
    float* Pb = P + ((size_t)bh * SS + m0) * SS;

    const unsigned int kh_s = (unsigned int)__cvta_generic_to_shared(Kh);
    const unsigned int vh_s = (unsigned int)__cvta_generic_to_shared(Vh);

    for (int ch = tid; ch < 1024; ch += 512) {
        int r = ch >> 3, c8 = (ch & 7) * 8;
        *(uint4*)&Qh[r * HLDA + c8] = *(const uint4*)&Qb[(size_t)r * DHD + c8];
    }
    if (tid < 128) ls[tid] = 0.0f;

    #pragma unroll
    for (int u = 0; u < 2; u++) {
        int ch = tid + u * 512;
        int r = ch >> 3, c8 = (ch & 7) * 8;
        cp_async16(kh_s + (unsigned int)((r * HLDA + c8) * 2), &Kb[(size_t)r * DHD + c8]);
        cp_async16(vh_s + (unsigned int)((r * HLDA + c8) * 2), &Vb[(size_t)r * DHD + c8]);
    }
    cp_commit();

    wmma::fragment<wmma::accumulator, 16, 16, 16, float> co[2];
    #pragma unroll
    for (int i = 0; i < 2; i++) wmma::fill_fragment(co[i], 0.0f);

    for (int kt = 0; kt <= qt; kt++) {
        const int vcur = (kt & 1) * HBUFA;
        cp_wait0();
        __syncthreads();

        wmma::fragment<wmma::accumulator, 16, 16, 16, float> cs[2][2];
        #pragma unroll
        for (int i = 0; i < 2; i++)
            #pragma unroll
            for (int j = 0; j < 2; j++)
                wmma::fill_fragment(cs[i][j], 0.0f);

        #pragma unroll
        for (int kk = 0; kk < 64; kk += 16) {
            wmma::fragment<wmma::matrix_a, 16, 16, 16, __half, wmma::row_major> a[2];
            wmma::fragment<wmma::matrix_b, 16, 16, 16, __half, wmma::col_major> b[2];
            #pragma unroll
            for (int i = 0; i < 2; i++)
                wmma::load_matrix_sync(a[i], &Qh[(wm * 32 + i * 16) * HLDA + kk], HLDA);
            #pragma unroll
            for (int j = 0; j < 2; j++)
                wmma::load_matrix_sync(b[j], &Kh[(wn * 32 + j * 16) * HLDA + kk], HLDA);
            #pragma unroll
            for (int i = 0; i < 2; i++)
                #pragma unroll
                for (int j = 0; j < 2; j++)
                    wmma::mma_sync(cs[i][j], a[i], b[j], cs[i][j]);
        }
        #pragma unroll
        for (int i = 0; i < 2; i++)
            #pragma unroll
            for (int j = 0; j < 2; j++)
                wmma::store_matrix_sync(&Ss[(wm * 32 + i * 16) * 132 + wn * 32 + j * 16],
                                        cs[i][j], 132, wmma::mem_row_major);
        __syncthreads();

        if (kt < qt) {
            const int k1 = (kt + 1) * 128;
            const unsigned int vdst = vh_s + (unsigned int)((((kt + 1) & 1) * HBUFA) * 2);
            #pragma unroll
            for (int u = 0; u < 2; u++) {
                int ch = tid + u * 512;
                int r = ch >> 3, c8 = (ch & 7) * 8;
                cp_async16(kh_s + (unsigned int)((r * HLDA + c8) * 2),
                           &Kb[(size_t)(k1 + r) * DHD + c8]);
                cp_async16(vdst + (unsigned int)((r * HLDA + c8) * 2),
                           &Vb[(size_t)(k1 + r) * DHD + c8]);
            }
            cp_commit();
        }

        {
            const int k0 = kt * 128;
            int r  = tid >> 2;
            int c0 = (tid & 3) * 32;
            int grow = m0 + r;
            float partial = 0.0f;
            #pragma unroll
            for (int c = 0; c < 32; c += 4) {
                int gc = k0 + c0 + c;
                float4 v = *(float4*)&Ss[r * 132 + c0 + c];
                v.x = (gc + 0 <= grow) ? fexp8(v.x) : 0.0f;
                v.y = (gc + 1 <= grow) ? fexp8(v.y) : 0.0f;
                v.z = (gc + 2 <= grow) ? fexp8(v.z) : 0.0f;
                v.w = (gc + 3 <= grow) ? fexp8(v.w) : 0.0f;
                partial += v.x + v.y + v.z + v.w;
                *(float4*)&Pb[(size_t)r * SS + gc] = v;
                __half* ed = &Es[r * 136 + c0 + c];
                *(__half2*)&ed[0] = __floats2half2_rn(v.x, v.y);
                *(__half2*)&ed[2] = __floats2half2_rn(v.z, v.w);
            }
            atomicAdd(&ls[r], partial);
        }
        __syncthreads();

        #pragma unroll
        for (int kk = 0; kk < 128; kk += 16) {
            wmma::fragment<wmma::matrix_a, 16, 16, 16, __half, wmma::row_major> a[2];
            wmma::fragment<wmma::matrix_b, 16, 16, 16, __half, wmma::row_major> b;
            #pragma unroll
            for (int i = 0; i < 2; i++)
                wmma::load_matrix_sync(a[i], &Es[(wm * 32 + i * 16) * 136 + kk], 136);
            wmma::load_matrix_sync(b, &Vh[vcur + kk * HLDA + wn * 16], HLDA);
            #pragma unroll
            for (int i = 0; i < 2; i++)
                wmma::mma_sync(co[i], a[i], b, co[i]);
        }
        __syncthreads();
    }

    const int zc0 = (qt + 1) * 128;
    if (zc0 < SS) {
        const int rl4 = (SS - zc0) >> 2;
        const float4 z4 = make_float4(0.f, 0.f, 0.f, 0.f);
        for (int i = tid; i < 128 * rl4; i += 512) {
            int r = i / rl4, c4 = (i - r * rl4) * 4;
            *(float4*)&Pb[(size_t)r * SS + zc0 + c4] = z4;
        }
    }

    #pragma unroll
    for (int i = 0; i < 2; i++)
        wmma::store_matrix_sync(&Ss[(wm * 32 + i * 16) * 68 + wn * 16],
                                co[i], 68, wmma::mem_row_major);
    __syncthreads();

    const int bi = bh / HH, hi = bh % HH;
    {
        int r  = tid >> 2;
        int c0 = (tid & 3) * 16;
        float inv = 1.0f / ls[r];
        __half* dsth = AVh + ((size_t)bi * SS + m0 + r) * DD + hi * DHD + c0;
        #pragma unroll
        for (int c = 0; c < 16; c += 4) {
            float4 v = *(float4*)&Ss[r * 68 + c0 + c];
            v.x *= inv; v.y *= inv; v.z *= inv; v.w *= inv;
            *(__half2*)&dsth[c]     = __floats2half2_rn(v.x, v.y);
            *(__half2*)&dsth[c + 2] = __floats2half2_rn(v.z, v.w);
        }
    }

    {
        const int rl4 = zc0 >> 2;
        for (int i = tid; i < 128 * rl4; i += 512) {
            int r = i / rl4, c4 = (i - r * rl4) * 4;
            float inv = 1.0f / ls[r];
            float4 v = *(float4*)&Pb[(size_t)r * SS + c4];
            v.x *= inv; v.y *= inv; v.z *= inv; v.w *= inv;
            *(float4*)&Pb[(size_t)r * SS + c4] = v;
        }
    }
}

// ---------------- fused residual add (+bias) + LayerNorm (+half copy) ------
__global__ void add_ln(const float* __restrict__ A, const float* __restrict__ Bv,
                       const float* __restrict__ bias,
                       const float* __restrict__ gamma, const float* __restrict__ beta,
                       float* __restrict__ out, __half* __restrict__ outh)
{
    const int row = blockIdx.x;
    const int tid = threadIdx.x;
    __shared__ float buf[DD];
    __shared__ float red[8];

    const float* a  = A  + (size_t)row * DD;
    const float* bp = Bv + (size_t)row * DD;

    float lsum = 0.f;
    #pragma unroll
    for (int i = 0; i < 3; i++) {
        int c = tid + i * 256;
        float v = a[c] + bp[c] + (bias ? bias[c] : 0.0f);
        buf[c] = v;
        lsum += v;
    }
    #pragma unroll
    for (int o = 16; o; o >>= 1) lsum += __shfl_xor_sync(0xffffffffu, lsum, o);
    if ((tid & 31) == 0) red[tid >> 5] = lsum;
    __syncthreads();
    float mu = (red[0]+red[1]+red[2]+red[3]+red[4]+red[5]+red[6]+red[7]) * (1.0f / DD);

    float lvar = 0.f;
    #pragma unroll
    for (int i = 0; i < 3; i++) {
        int c = tid + i * 256;
        float d = buf[c] - mu;
        lvar += d * d;
    }
    #pragma unroll
    for (int o = 16; o; o >>= 1) lvar += __shfl_xor_sync(0xffffffffu, lvar, o);
    __syncthreads();
    if ((tid & 31) == 0) red[tid >> 5] = lvar;
    __syncthreads();
    float var = (red[0]+red[1]+red[2]+red[3]+red[4]+red[5]+red[6]+red[7]) * (1.0f / DD);
    float inv = rsqrtf(var + 1e-5f);

    float* o = out + (size_t)row * DD;
    __half* oh = outh ? outh + (size_t)row * DD : nullptr;
    #pragma unroll
    for (int i = 0; i < 3; i++) {
        int c = tid + i * 256;
        float v = (buf[c] - mu) * inv * gamma[c] + beta[c];
        o[c] = v;
        if (oh) oh[c] = __float2half_rn(v);
    }
}

// ---------------------------------------------------------------------------
extern "C" void kernel_launch(void* const* d_in, const int* in_sizes, int n_in,
                              void* d_out, int out_size)
{
    const float* x   = (const float*)d_in[0];
    const float* Wq  = (const float*)d_in[2];
    const float* Wk  = (const float*)d_in[3];
    const float* Wv  = (const float*)d_in[4];
    const float* Wo  = (const float*)d_in[5];
    const float* bo  = (const float*)d_in[6];
    const float* g1  = (const float*)d_in[7];
    const float* b1  = (const float*)d_in[8];
    const float* W1  = (const float*)d_in[9];
    const float* bb1 = (const float*)d_in[10];
    const float* W2  = (const float*)d_in[11];
    const float* bb2 = (const float*)d_in[12];
    const float* g2  = (const float*)d_in[13];
    const float* b2  = (const float*)d_in[14];

    float* y = (float*)d_out;
    float* P = y + Y_ELEMS;

    float *aop, *hp, *f2p;
    __half *qh, *kh, *vh, *xh, *wqh, *wkh, *wvh, *woh, *w1h, *w2h, *avh, *hh, *f1h;
    cudaGetSymbolAddress((void**)&aop, g_ao);
    cudaGetSymbolAddress((void**)&hp,  g_h);
    cudaGetSymbolAddress((void**)&f2p, g_f2);
    cudaGetSymbolAddress((void**)&qh,  g_qh);
    cudaGetSymbolAddress((void**)&kh,  g_kh);
    cudaGetSymbolAddress((void**)&vh,  g_vh);
    cudaGetSymbolAddress((void**)&xh,  g_xh);
    cudaGetSymbolAddress((void**)&wqh, g_wqh);
    cudaGetSymbolAddress((void**)&wkh, g_wkh);
    cudaGetSymbolAddress((void**)&wvh, g_wvh);
    cudaGetSymbolAddress((void**)&woh, g_woh);
    cudaGetSymbolAddress((void**)&w1h, g_w1h);
    cudaGetSymbolAddress((void**)&w2h, g_w2h);
    cudaGetSymbolAddress((void**)&avh, g_avh);
    cudaGetSymbolAddress((void**)&hh,  g_hh);
    cudaGetSymbolAddress((void**)&f1h, g_f1h);

    cudaFuncSetAttribute(gemm_h, cudaFuncAttributeMaxDynamicSharedMemorySize, GEMMH_SMEM_BYTES);
    cudaFuncSetAttribute(gemm_h_gelu, cudaFuncAttributeMaxDynamicSharedMemorySize, GEMMH_SMEM_BYTES);
    cudaFuncSetAttribute(qkv_gemm_h, cudaFuncAttributeMaxDynamicSharedMemorySize, GEMMH_SMEM_BYTES);
    cudaFuncSetAttribute(attn_fused, cudaFuncAttributeMaxDynamicSharedMemorySize, ATT_SMEM_BYTES);

    // fp16 conversions
    f2h<<<(MM*DD)/1024, 256>>>(x,  xh);
    f2h<<<(DD*DD)/1024, 256>>>(Wq, wqh);
    f2h<<<(DD*DD)/1024, 256>>>(Wk, wkh);
    f2h<<<(DD*DD)/1024, 256>>>(Wv, wvh);
    f2h<<<(DD*DD)/1024, 256>>>(Wo, woh);
    f2h<<<(DFF*DD)/1024, 256>>>(W1, w1h);
    f2h<<<(DD*DFF)/1024, 256>>>(W2, w2h);

    dim3 g768 (DD  / 128, MM / 256);     // (6, 16)
    dim3 g3072(DFF / 128, MM / 256);     // (24, 16)
    dim3 gqkv (DD  / 128, MM / 256, 3);

    // QKV projections (fp16 in, fp16 head-split out)
    qkv_gemm_h<<<gqkv, 256, GEMMH_SMEM_BYTES>>>(xh, wqh, wkh, wvh, qh, kh, vh);

    // fused attention (fp16 MMA) -> P fp32, AV fp16
    attn_fused<<<dim3(SS / 128, BB * HH), 512, ATT_SMEM_BYTES>>>(qh, kh, vh, P, avh);

    // output projection
    gemm_h<<<g768, 256, GEMMH_SMEM_BYTES>>>(avh, woh, aop, DD, DD);

    // h = LN(x + attn_out + bo) -> fp32 + fp16
    add_ln<<<MM, 256>>>(x, aop, bo, g1, b1, hp, hh);

    // FFN1 + bias + GELU fused -> fp16
    gemm_h_gelu<<<g3072, 256, GEMMH_SMEM_BYTES>>>(hh, w1h, bb1, f1h, DFF, DD);

    // FFN2
    gemm_h<<<g768, 256, GEMMH_SMEM_BYTES>>>(f1h, w2h, f2p, DD, DFF);

    // y = LN(h + f + bb2)
    add_ln<<<MM, 256>>>(hp, f2p, bb2, g2, b2, y, nullptr);
}

// round 15
// speedup vs baseline: 1.1327x; 1.1327x over previous
#include <cuda_runtime.h>
#include <cuda_fp16.h>
#include <cstdint>
#include <math.h>
#include <mma.h>

using namespace nvcuda;

// Problem constants
#define BB 2
#define SS 2048
#define HH 12
#define DHD 64
#define DD 768
#define DFF 3072
#define MM (BB*SS)
#define Y_ELEMS ((size_t)BB*SS*DD)

// ---------------- scratch (device globals) ---------------------------------
__device__ float g_ao[BB*SS*DD];
__device__ float g_h [BB*SS*DD];
__device__ float g_f2[BB*SS*DD];

// fp16 buffers
__device__ __half g_qh [BB*HH*SS*DHD];
__device__ __half g_kh [BB*HH*SS*DHD];
__device__ __half g_vh [BB*HH*SS*DHD];
__device__ __half g_xh [BB*SS*DD];
__device__ __half g_wqh[DD*DD];
__device__ __half g_wkh[DD*DD];
__device__ __half g_wvh[DD*DD];
__device__ __half g_woh[DD*DD];
__device__ __half g_w1h[DFF*DD];
__device__ __half g_w2h[DD*DFF];
__device__ __half g_avh[BB*SS*DD];
__device__ __half g_hh [BB*SS*DD];
__device__ __half g_f1h[BB*SS*DFF];

__device__ __forceinline__ void cp_async16(unsigned int dst, const void* src) {
    asm volatile("cp.async.cg.shared.global [%0], [%1], 16;\n" :: "r"(dst), "l"(src));
}
__device__ __forceinline__ void cp_commit() {
    asm volatile("cp.async.commit_group;\n");
}
__device__ __forceinline__ void cp_wait0() {
    asm volatile("cp.async.wait_group 0;\n");
}
__device__ __forceinline__ void cp_wait1() {
    asm volatile("cp.async.wait_group 1;\n");
}
// streaming 16B store (evict-first: don't pollute L2 with never-re-read data)
__device__ __forceinline__ void st_cs16(float* p, float4 v) {
    asm volatile("st.global.cs.v4.f32 [%0], {%1,%2,%3,%4};\n"
                 :: "l"(p), "f"(v.x), "f"(v.y), "f"(v.z), "f"(v.w));
}

// FMA-pipe exp of (x * 1/8)
__device__ __forceinline__ float fexp8(float x) {
    float t  = fmaxf(x * 0.18033688011112042f, -115.0f);
    float fi = rintf(t);
    float f  = t - fi;
    float p  = 1.3393036e-3f;
    p = fmaf(p, f, 9.6181316e-3f);
    p = fmaf(p, f, 5.5504109e-2f);
    p = fmaf(p, f, 2.4022651e-1f);
    p = fmaf(p, f, 6.9314718e-1f);
    p = fmaf(p, f, 1.0f);
    return __int_as_float(__float_as_int(p) + ((int)fi << 23));
}

// ------------- fused fp32 -> fp16 convert (all tensors, one launch) --------
// segments: 0:x(3072 blk) 1..4:Wq/Wk/Wv/Wo(576 each) 5:W1(2304) 6:W2(2304)
__global__ void f2h_all(const float* __restrict__ x,  __half* __restrict__ xh,
                        const float* __restrict__ wq, __half* __restrict__ wqh,
                        const float* __restrict__ wk, __half* __restrict__ wkh,
                        const float* __restrict__ wv, __half* __restrict__ wvh,
                        const float* __restrict__ wo, __half* __restrict__ woh,
                        const float* __restrict__ w1, __half* __restrict__ w1h,
                        const float* __restrict__ w2, __half* __restrict__ w2h)
{
    int blk = blockIdx.x;
    const float* in; __half* out;
    if      (blk < 3072)            { in = x;  out = xh;  }
    else if (blk < 3648)            { in = wq; out = wqh; blk -= 3072; }
    else if (blk < 4224)            { in = wk; out = wkh; blk -= 3648; }
    else if (blk < 4800)            { in = wv; out = wvh; blk -= 4224; }
    else if (blk < 5376)            { in = wo; out = woh; blk -= 4800; }
    else if (blk < 7680)            { in = w1; out = w1h; blk -= 5376; }
    else                            { in = w2; out = w2h; blk -= 7680; }
    const size_t i = ((size_t)blk * 256 + threadIdx.x) * 4;
    float4 v = *(const float4*)&in[i];
    *(__half2*)&out[i]     = __floats2half2_rn(v.x, v.y);
    *(__half2*)&out[i + 2] = __floats2half2_rn(v.z, v.w);
}
#define F2H_ALL_BLOCKS 9984   // 3072+4*576+2304+2304

// ============  fp16 NT GEMM, 3-stage cp.async (R13 proven config) ==========
#define HLD 72
#define HBUF (128*HLD)
#define GSTG 3
#define GEMMH_SMEM_BYTES (GSTG*2*HBUF*2)     // 110,592 B

// MODE 0: fp32 C. MODE 2: bias+GELU -> half C. MODE 4: head-split half C.
template<int MODE>
__device__ __forceinline__ void gemm_h_body(const __half* __restrict__ A,
                                            const __half* __restrict__ B,
                                            const float* __restrict__ bias,
                                            void* __restrict__ Cv,
                                            int N, int K, int m0, int n0)
{
    extern __shared__ float gsm[];
    __half* As = (__half*)gsm;               // [GSTG][128][72]
    __half* Bs = As + GSTG*HBUF;

    const int tid  = threadIdx.x;            // 256
    const int warp = tid >> 5;
    const int wm   = warp & 1;
    const int wn   = warp >> 1;

    const unsigned int as_s = (unsigned int)__cvta_generic_to_shared(As);
    const unsigned int bs_s = (unsigned int)__cvta_generic_to_shared(Bs);

    wmma::fragment<wmma::accumulator, 16, 16, 16, float> c[4][2];
    #pragma unroll
    for (int i = 0; i < 4; i++)
        #pragma unroll
        for (int j = 0; j < 2; j++)
            wmma::fill_fragment(c[i][j], 0.0f);

    const int T = K >> 6;

    auto issue = [&](int t) {
        const int k0 = t << 6;
        const unsigned int soff = (unsigned int)((t % GSTG) * HBUF * 2);
        #pragma unroll
        for (int i = 0; i < 4; i++) {
            int ch   = tid + i * 256;
            int row  = ch >> 3;
            int col8 = (ch & 7) * 8;
            cp_async16(as_s + soff + (unsigned int)((row * HLD + col8) * 2),
                       &A[(size_t)(m0 + row) * K + k0 + col8]);
            cp_async16(bs_s + soff + (unsigned int)((row * HLD + col8) * 2),
                       &B[(size_t)(n0 + row) * K + k0 + col8]);
        }
        cp_commit();
    };

    issue(0);
    if (T > 1) issue(1);

    for (int t = 0; t < T; t++) {
        if (t + 1 < T) cp_wait1(); else cp_wait0();
        __syncthreads();
        if (t + 2 < T) issue(t + 2);

        const int cur = (t % GSTG) * HBUF;
        #pragma unroll
        for (int kk = 0; kk < 64; kk += 16) {
            wmma::fragment<wmma::matrix_a, 16, 16, 16, __half, wmma::row_major> a[4];
            wmma::fragment<wmma::matrix_b, 16, 16, 16, __half, wmma::col_major> b[2];
            #pragma unroll
            for (int i = 0; i < 4; i++)
                wmma::load_matrix_sync(a[i], &As[cur + (wm * 64 + i * 16) * HLD + kk], HLD);
            #pragma unroll
            for (int j = 0; j < 2; j++)
                wmma::load_matrix_sync(b[j], &Bs[cur + (wn * 32 + j * 16) * HLD + kk], HLD);
            #pragma unroll
            for (int i = 0; i < 4; i++)
                #pragma unroll
                for (int j = 0; j < 2; j++)
                    wmma::mma_sync(c[i][j], a[i], b[j], c[i][j]);
        }
        __syncthreads();
    }

    if (MODE == 2 || MODE == 4) {
        float* stg = gsm;                    // [128][132]
        #pragma unroll
        for (int i = 0; i < 4; i++)
            #pragma unroll
            for (int j = 0; j < 2; j++)
                wmma::store_matrix_sync(&stg[(wm * 64 + i * 16) * 132 + wn * 32 + j * 16],
                                        c[i][j], 132, wmma::mem_row_major);
        __syncthreads();
        __half* C = (__half*)Cv;
        const int r  = tid >> 1;
        const int c0 = (tid & 1) * 64;
        if (MODE == 2) {
            #pragma unroll
            for (int cc = 0; cc < 64; cc += 4) {
                float4 v = *(float4*)&stg[r * 132 + c0 + cc];
                float4 bb = *(const float4*)&bias[n0 + c0 + cc];
                v.x += bb.x; v.y += bb.y; v.z += bb.z; v.w += bb.w;
                v.x = 0.5f * v.x * (1.0f + erff(v.x * 0.70710678118654752f));
                v.y = 0.5f * v.y * (1.0f + erff(v.y * 0.70710678118654752f));
                v.z = 0.5f * v.z * (1.0f + erff(v.z * 0.70710678118654752f));
                v.w = 0.5f * v.w * (1.0f + erff(v.w * 0.70710678118654752f));
                __half* dst = &C[(size_t)(m0 + r) * N + n0 + c0 + cc];
                *(__half2*)&dst[0] = __floats2half2_rn(v.x, v.y);
                *(__half2*)&dst[2] = __floats2half2_rn(v.z, v.w);
            }
        } else {
            int m = m0 + r;
            int bidx = m >> 11, s = m & 2047;
            int h = (n0 + c0) >> 6;
            __half* dst = &C[(((size_t)(bidx * HH + h)) * SS + s) * DHD];
            #pragma unroll
            for (int cc = 0; cc < 64; cc += 4) {
                float4 v = *(float4*)&stg[r * 132 + c0 + cc];
                *(__half2*)&dst[cc]     = __floats2half2_rn(v.x, v.y);
                *(__half2*)&dst[cc + 2] = __floats2half2_rn(v.z, v.w);
            }
        }
    } else {
        float* C = (float*)Cv;
        #pragma unroll
        for (int i = 0; i < 4; i++) {
            int m = m0 + wm * 64 + i * 16;
            #pragma unroll
            for (int j = 0; j < 2; j++) {
                int n = n0 + wn * 32 + j * 16;
                wmma::store_matrix_sync(C + (size_t)m * N + n, c[i][j], N, wmma::mem_row_major);
            }
        }
    }
}

__global__ void __launch_bounds__(256)
gemm_h(const __half* __restrict__ A, const __half* __restrict__ B,
       float* __restrict__ C, int N, int K)
{
    gemm_h_body<0>(A, B, nullptr, C, N, K, blockIdx.y * 128, blockIdx.x * 128);
}

__global__ void __launch_bounds__(256)
gemm_h_gelu(const __half* __restrict__ A, const __half* __restrict__ B,
            const float* __restrict__ bias, __half* __restrict__ C, int N, int K)
{
    gemm_h_body<2>(A, B, bias, C, N, K, blockIdx.y * 128, blockIdx.x * 128);
}

__global__ void __launch_bounds__(256)
qkv_gemm_h(const __half* __restrict__ X,
           const __half* __restrict__ Wq, const __half* __restrict__ Wk,
           const __half* __restrict__ Wv,
           __half* __restrict__ Qo, __half* __restrict__ Ko, __half* __restrict__ Vo)
{
    const __half* B = (blockIdx.z == 0) ? Wq : (blockIdx.z == 1) ? Wk : Wv;
    __half*       C = (blockIdx.z == 0) ? Qo : (blockIdx.z == 1) ? Ko : Vo;
    gemm_h_body<4>(X, B, nullptr, C, DD, DD, blockIdx.y * 128, blockIdx.x * 128);
}

// ==============  fused flash attention, fp16 MMA, cp.async  ================
#define AT_QH 0
#define AT_KH 18432
#define AT_VH 36864
#define AT_SS 73728
#define AT_ES 141312
#define AT_LS 176128
#define ATT_SMEM_BYTES 176640
#define HLDA 72
#define HBUFA (128*HLDA)

__global__ void __launch_bounds__(512, 1)
attn_fused(const __half* __restrict__ Q, const __half* __restrict__ K,
           const __half* __restrict__ V, float* __restrict__ P,
           __half* __restrict__ AVh)
{
    extern __shared__ char smraw[];
    __half* Qh = (__half*)(smraw + AT_QH);
    __half* Kh = (__half*)(smraw + AT_KH);
    __half* Vh = (__half*)(smraw + AT_VH);
    float*  Ss = (float*)(smraw + AT_SS);
    __half* Es = (__half*)(smraw + AT_ES);
    float*  ls = (float*)(smraw + AT_LS);

    const int bh  = blockIdx.y;
    const int qt  = gridDim.x - 1 - blockIdx.x;
    const int m0  = qt * 128;
    const int tid = threadIdx.x;
    const int warp = tid >> 5;
    const int wm = warp & 3;
    const int wn = warp >> 2;

    const __half* Qb = Q + ((size_t)bh * SS + m0) * DHD;
    const __half* Kb = K + (size_t)bh * SS * DHD;
    const __half* Vb = V + (size_t)bh * SS * DHD;
    float* Pb = P + ((size_t)bh * SS + m0) * SS;

    const unsigned int kh_s = (unsigned int)__cvta_generic_to_shared(Kh);
    const unsigned int vh_s = (unsigned int)__cvta_generic_to_shared(Vh);

    for (int ch = tid; ch < 1024; ch += 512) {
        int r = ch >> 3, c8 = (ch & 7) * 8;
        *(uint4*)&Qh[r * HLDA + c8] = *(const uint4*)&Qb[(size_t)r * DHD + c8];
    }
    if (tid < 128) ls[tid] = 0.0f;

    #pragma unroll
    for (int u = 0; u < 2; u++) {
        int ch = tid + u * 512;
        int r = ch >> 3, c8 = (ch & 7) * 8;
        cp_async16(kh_s + (unsigned int)((r * HLDA + c8) * 2), &Kb[(size_t)r * DHD + c8]);
        cp_async16(vh_s + (unsigned int)((r * HLDA + c8) * 2), &Vb[(size_t)r * DHD + c8]);
    }
    cp_commit();

    wmma::fragment<wmma::accumulator, 16, 16, 16, float> co[2];
    #pragma unroll
    for (int i = 0; i < 2; i++) wmma::fill_fragment(co[i], 0.0f);

    for (int kt = 0; kt <= qt; kt++) {
        const int vcur = (kt & 1) * HBUFA;
        cp_wait0();
        __syncthreads();

        wmma::fragment<wmma::accumulator, 16, 16, 16, float> cs[2][2];
        #pragma unroll
        for (int i = 0; i < 2; i++)
            #pragma unroll
            for (int j = 0; j < 2; j++)
                wmma::fill_fragment(cs[i][j], 0.0f);

        #pragma unroll
        for (int kk = 0; kk < 64; kk += 16) {
            wmma::fragment<wmma::matrix_a, 16, 16, 16, __half, wmma::row_major> a[2];
            wmma::fragment<wmma::matrix_b, 16, 16, 16, __half, wmma::col_major> b[2];
            #pragma unroll
            for (int i = 0; i < 2; i++)
                wmma::load_matrix_sync(a[i], &Qh[(wm * 32 + i * 16) * HLDA + kk], HLDA);
            #pragma unroll
            for (int j = 0; j < 2; j++)
                wmma::load_matrix_sync(b[j], &Kh[(wn * 32 + j * 16) * HLDA + kk], HLDA);
            #pragma unroll
            for (int i = 0; i < 2; i++)
                #pragma unroll
                for (int j = 0; j < 2; j++)
                    wmma::mma_sync(cs[i][j], a[i], b[j], cs[i][j]);
        }
        #pragma unroll
        for (int i = 0; i < 2; i++)
            #pragma unroll
            for (int j = 0; j < 2; j++)
                wmma::store_matrix_sync(&Ss[(wm * 32 + i * 16) * 132 + wn * 32 + j * 16],
                                        cs[i][j], 132, wmma::mem_row_major);
        __syncthreads();

        if (kt < qt) {
            const int k1 = (kt + 1) * 128;
            const unsigned int vdst = vh_s + (unsigned int)((((kt + 1) & 1) * HBUFA) * 2);
            #pragma unroll
            for (int u = 0; u < 2; u++) {
                int ch = tid + u * 512;
                int r = ch >> 3, c8 = (ch & 7) * 8;
                cp_async16(kh_s + (unsigned int)((r * HLDA + c8) * 2),
                           &Kb[(size_t)(k1 + r) * DHD + c8]);
                cp_async16(vdst + (unsigned int)((r * HLDA + c8) * 2),
                           &Vb[(size_t)(k1 + r) * DHD + c8]);
            }
            cp_commit();
        }

        {
            const int k0 = kt * 128;
            int r  = tid >> 2;
            int c0 = (tid & 3) * 32;
            int grow = m0 + r;
            float partial = 0.0f;
            #pragma unroll
            for (int c = 0; c < 32; c += 4) {
                int gc = k0 + c0 + c;
                float4 v = *(float4*)&Ss[r * 132 + c0 + c];
                v.x = (gc + 0 <= grow) ? fexp8(v.x) : 0.0f;
                v.y = (gc + 1 <= grow) ? fexp8(v.y) : 0.0f;
                v.z = (gc + 2 <= grow) ? fexp8(v.z) : 0.0f;
                v.w = (gc + 3 <= grow) ? fexp8(v.w) : 0.0f;
                partial += v.x + v.y + v.z + v.w;
                *(float4*)&Pb[(size_t)r * SS + gc] = v;
                __half* ed = &Es[r * 136 + c0 + c];
                *(__half2*)&ed[0] = __floats2half2_rn(v.x, v.y);
                *(__half2*)&ed[2] = __floats2half2_rn(v.z, v.w);
            }
            atomicAdd(&ls[r], partial);
        }
        __syncthreads();

        #pragma unroll
        for (int kk = 0; kk < 128; kk += 16) {
            wmma::fragment<wmma::matrix_a, 16, 16, 16, __half, wmma::row_major> a[2];
            wmma::fragment<wmma::matrix_b, 16, 16, 16, __half, wmma::row_major> b;
            #pragma unroll
            for (int i = 0; i < 2; i++)
                wmma::load_matrix_sync(a[i], &Es[(wm * 32 + i * 16) * 136 + kk], 136);
            wmma::load_matrix_sync(b, &Vh[vcur + kk * HLDA + wn * 16], HLDA);
            #pragma unroll
            for (int i = 0; i < 2; i++)
                wmma::mma_sync(co[i], a[i], b, co[i]);
        }
        __syncthreads();
    }

    // zero-fill fully masked P region (streaming stores — never re-read)
    const int zc0 = (qt + 1) * 128;
    if (zc0 < SS) {
        const int rl4 = (SS - zc0) >> 2;
        const float4 z4 = make_float4(0.f, 0.f, 0.f, 0.f);
        for (int i = tid; i < 128 * rl4; i += 512) {
            int r = i / rl4, c4 = (i - r * rl4) * 4;
            st_cs16(&Pb[(size_t)r * SS + zc0 + c4], z4);
        }
    }

    // stage O to smem (reuse Ss, ld 68), normalize, write AVh
    #pragma unroll
    for (int i = 0; i < 2; i++)
        wmma::store_matrix_sync(&Ss[(wm * 32 + i * 16) * 68 + wn * 16],
                                co[i], 68, wmma::mem_row_major);
    __syncthreads();

    const int bi = bh / HH, hi = bh % HH;
    {
        int r  = tid >> 2;
        int c0 = (tid & 3) * 16;
        float inv = 1.0f / ls[r];
        __half* dsth = AVh + ((size_t)bi * SS + m0 + r) * DD + hi * DHD + c0;
        #pragma unroll
        for (int c = 0; c < 16; c += 4) {
            float4 v = *(float4*)&Ss[r * 68 + c0 + c];
            v.x *= inv; v.y *= inv; v.z *= inv; v.w *= inv;
            *(__half2*)&dsth[c]     = __floats2half2_rn(v.x, v.y);
            *(__half2*)&dsth[c + 2] = __floats2half2_rn(v.z, v.w);
        }
    }

    // rescale lower-triangle P by 1/rowsum (streaming final writes)
    {
        const int rl4 = zc0 >> 2;
        for (int i = tid; i < 128 * rl4; i += 512) {
            int r = i / rl4, c4 = (i - r * rl4) * 4;
            float inv = 1.0f / ls[r];
            float4 v = *(float4*)&Pb[(size_t)r * SS + c4];
            v.x *= inv; v.y *= inv; v.z *= inv; v.w *= inv;
            st_cs16(&Pb[(size_t)r * SS + c4], v);
        }
    }
}

// ---------------- fused residual add (+bias) + LayerNorm (+half copy) ------
__global__ void add_ln(const float* __restrict__ A, const float* __restrict__ Bv,
                       const float* __restrict__ bias,
                       const float* __restrict__ gamma, const float* __restrict__ beta,
                       float* __restrict__ out, __half* __restrict__ outh)
{
    const int row = blockIdx.x;
    const int tid = threadIdx.x;
    __shared__ float buf[DD];
    __shared__ float red[8];

    const float* a  = A  + (size_t)row * DD;
    const float* bp = Bv + (size_t)row * DD;

    float lsum = 0.f;
    #pragma unroll
    for (int i = 0; i < 3; i++) {
        int c = tid + i * 256;
        float v = a[c] + bp[c] + (bias ? bias[c] : 0.0f);
        buf[c] = v;
        lsum += v;
    }
    #pragma unroll
    for (int o = 16; o; o >>= 1) lsum += __shfl_xor_sync(0xffffffffu, lsum, o);
    if ((tid & 31) == 0) red[tid >> 5] = lsum;
    __syncthreads();
    float mu = (red[0]+red[1]+red[2]+red[3]+red[4]+red[5]+red[6]+red[7]) * (1.0f / DD);

    float lvar = 0.f;
    #pragma unroll
    for (int i = 0; i < 3; i++) {
        int c = tid + i * 256;
        float d = buf[c] - mu;
        lvar += d * d;
    }
    #pragma unroll
    for (int o = 16; o; o >>= 1) lvar += __shfl_xor_sync(0xffffffffu, lvar, o);
    __syncthreads();
    if ((tid & 31) == 0) red[tid >> 5] = lvar;
    __syncthreads();
    float var = (red[0]+red[1]+red[2]+red[3]+red[4]+red[5]+red[6]+red[7]) * (1.0f / DD);
    float inv = rsqrtf(var + 1e-5f);

    float* o = out + (size_t)row * DD;
    __half* oh = outh ? outh + (size_t)row * DD : nullptr;
    #pragma unroll
    for (int i = 0; i < 3; i++) {
        int c = tid + i * 256;
        float v = (buf[c] - mu) * inv * gamma[c] + beta[c];
        o[c] = v;
        if (oh) oh[c] = __float2half_rn(v);
    }
}

// ---------------------------------------------------------------------------
extern "C" void kernel_launch(void* const* d_in, const int* in_sizes, int n_in,
                              void* d_out, int out_size)
{
    const float* x   = (const float*)d_in[0];
    const float* Wq  = (const float*)d_in[2];
    const float* Wk  = (const float*)d_in[3];
    const float* Wv  = (const float*)d_in[4];
    const float* Wo  = (const float*)d_in[5];
    const float* bo  = (const float*)d_in[6];
    const float* g1  = (const float*)d_in[7];
    const float* b1  = (const float*)d_in[8];
    const float* W1  = (const float*)d_in[9];
    const float* bb1 = (const float*)d_in[10];
    const float* W2  = (const float*)d_in[11];
    const float* bb2 = (const float*)d_in[12];
    const float* g2  = (const float*)d_in[13];
    const float* b2  = (const float*)d_in[14];

    float* y = (float*)d_out;
    float* P = y + Y_ELEMS;

    float *aop, *hp, *f2p;
    __half *qh, *kh, *vh, *xh, *wqh, *wkh, *wvh, *woh, *w1h, *w2h, *avh, *hh, *f1h;
    cudaGetSymbolAddress((void**)&aop, g_ao);
    cudaGetSymbolAddress((void**)&hp,  g_h);
    cudaGetSymbolAddress((void**)&f2p, g_f2);
    cudaGetSymbolAddress((void**)&qh,  g_qh);
    cudaGetSymbolAddress((void**)&kh,  g_kh);
    cudaGetSymbolAddress((void**)&vh,  g_vh);
    cudaGetSymbolAddress((void**)&xh,  g_xh);
    cudaGetSymbolAddress((void**)&wqh, g_wqh);
    cudaGetSymbolAddress((void**)&wkh, g_wkh);
    cudaGetSymbolAddress((void**)&wvh, g_wvh);
    cudaGetSymbolAddress((void**)&woh, g_woh);
    cudaGetSymbolAddress((void**)&w1h, g_w1h);
    cudaGetSymbolAddress((void**)&w2h, g_w2h);
    cudaGetSymbolAddress((void**)&avh, g_avh);
    cudaGetSymbolAddress((void**)&hh,  g_hh);
    cudaGetSymbolAddress((void**)&f1h, g_f1h);

    cudaFuncSetAttribute(gemm_h, cudaFuncAttributeMaxDynamicSharedMemorySize, GEMMH_SMEM_BYTES);
    cudaFuncSetAttribute(gemm_h_gelu, cudaFuncAttributeMaxDynamicSharedMemorySize, GEMMH_SMEM_BYTES);
    cudaFuncSetAttribute(qkv_gemm_h, cudaFuncAttributeMaxDynamicSharedMemorySize, GEMMH_SMEM_BYTES);
    cudaFuncSetAttribute(attn_fused, cudaFuncAttributeMaxDynamicSharedMemorySize, ATT_SMEM_BYTES);

    // all fp32->fp16 conversions in one launch
    f2h_all<<<F2H_ALL_BLOCKS, 256>>>(x, xh, Wq, wqh, Wk, wkh, Wv, wvh,
                                     Wo, woh, W1, w1h, W2, w2h);

    dim3 g768 (DD  / 128, MM / 128);
    dim3 g3072(DFF / 128, MM / 128);
    dim3 gqkv (DD  / 128, MM / 128, 3);

    // QKV projections (fp16 in, fp16 head-split out)
    qkv_gemm_h<<<gqkv, 256, GEMMH_SMEM_BYTES>>>(xh, wqh, wkh, wvh, qh, kh, vh);

    // fused attention (fp16 MMA) -> P fp32, AV fp16
    attn_fused<<<dim3(SS / 128, BB * HH), 512, ATT_SMEM_BYTES>>>(qh, kh, vh, P, avh);

    // output projection
    gemm_h<<<g768, 256, GEMMH_SMEM_BYTES>>>(avh, woh, aop, DD, DD);

    // h = LN(x + attn_out + bo) -> fp32 + fp16
    add_ln<<<MM, 256>>>(x, aop, bo, g1, b1, hp, hh);

    // FFN1 + bias + GELU fused -> fp16
    gemm_h_gelu<<<g3072, 256, GEMMH_SMEM_BYTES>>>(hh, w1h, bb1, f1h, DFF, DD);

    // FFN2
    gemm_h<<<g768, 256, GEMMH_SMEM_BYTES>>>(f1h, w2h, f2p, DD, DFF);

    // y = LN(h + f + bb2)
    add_ln<<<MM, 256>>>(hp, f2p, bb2, g2, b2, y, nullptr);
}

// round 16
// speedup vs baseline: 1.1458x; 1.0116x over previous
#include <cuda_runtime.h>
#include <cuda_fp16.h>
#include <cstdint>
#include <math.h>
#include <mma.h>

using namespace nvcuda;

// Problem constants
#define BB 2
#define SS 2048
#define HH 12
#define DHD 64
#define DD 768
#define DFF 3072
#define MM (BB*SS)
#define Y_ELEMS ((size_t)BB*SS*DD)

// ---------------- scratch (device globals) ---------------------------------
__device__ float g_ao[BB*SS*DD];
__device__ float g_h [BB*SS*DD];
__device__ float g_f2[BB*SS*DD];

// fp16 buffers
__device__ __half g_qh [BB*HH*SS*DHD];
__device__ __half g_kh [BB*HH*SS*DHD];
__device__ __half g_vh [BB*HH*SS*DHD];
__device__ __half g_xh [BB*SS*DD];
__device__ __half g_wqh[DD*DD];
__device__ __half g_wkh[DD*DD];
__device__ __half g_wvh[DD*DD];
__device__ __half g_woh[DD*DD];
__device__ __half g_w1h[DFF*DD];
__device__ __half g_w2h[DD*DFF];
__device__ __half g_avh[BB*SS*DD];
__device__ __half g_hh [BB*SS*DD];
__device__ __half g_f1h[BB*SS*DFF];

__device__ __forceinline__ void cp_async16(unsigned int dst, const void* src) {
    asm volatile("cp.async.cg.shared.global [%0], [%1], 16;\n" :: "r"(dst), "l"(src));
}
__device__ __forceinline__ void cp_commit() {
    asm volatile("cp.async.commit_group;\n");
}
__device__ __forceinline__ void cp_wait0() {
    asm volatile("cp.async.wait_group 0;\n");
}
// streaming 16B store (evict-first)
__device__ __forceinline__ void st_cs16(float* p, float4 v) {
    asm volatile("st.global.cs.v4.f32 [%0], {%1,%2,%3,%4};\n"
                 :: "l"(p), "f"(v.x), "f"(v.y), "f"(v.z), "f"(v.w));
}

// FMA-pipe exp of (x * 1/8)
__device__ __forceinline__ float fexp8(float x) {
    float t  = fmaxf(x * 0.18033688011112042f, -115.0f);
    float fi = rintf(t);
    float f  = t - fi;
    float p  = 1.3393036e-3f;
    p = fmaf(p, f, 9.6181316e-3f);
    p = fmaf(p, f, 5.5504109e-2f);
    p = fmaf(p, f, 2.4022651e-1f);
    p = fmaf(p, f, 6.9314718e-1f);
    p = fmaf(p, f, 1.0f);
    return __int_as_float(__float_as_int(p) + ((int)fi << 23));
}

// ------------- fused fp32 -> fp16 convert (all tensors, one launch) --------
__global__ void f2h_all(const float* __restrict__ x,  __half* __restrict__ xh,
                        const float* __restrict__ wq, __half* __restrict__ wqh,
                        const float* __restrict__ wk, __half* __restrict__ wkh,
                        const float* __restrict__ wv, __half* __restrict__ wvh,
                        const float* __restrict__ wo, __half* __restrict__ woh,
                        const float* __restrict__ w1, __half* __restrict__ w1h,
                        const float* __restrict__ w2, __half* __restrict__ w2h)
{
    int blk = blockIdx.x;
    const float* in; __half* out;
    if      (blk < 3072)            { in = x;  out = xh;  }
    else if (blk < 3648)            { in = wq; out = wqh; blk -= 3072; }
    else if (blk < 4224)            { in = wk; out = wkh; blk -= 3648; }
    else if (blk < 4800)            { in = wv; out = wvh; blk -= 4224; }
    else if (blk < 5376)            { in = wo; out = woh; blk -= 4800; }
    else if (blk < 7680)            { in = w1; out = w1h; blk -= 5376; }
    else                            { in = w2; out = w2h; blk -= 7680; }
    const size_t i = ((size_t)blk * 256 + threadIdx.x) * 4;
    float4 v = *(const float4*)&in[i];
    *(__half2*)&out[i]     = __floats2half2_rn(v.x, v.y);
    *(__half2*)&out[i + 2] = __floats2half2_rn(v.z, v.w);
}
#define F2H_ALL_BLOCKS 9984

// ======  fp16 NT GEMM, 2-stage cp.async, 2 CTAs/SM (regs fit at 128) ======
#define HLD 72
#define HBUF (128*HLD)
#define GSTG 2
#define GEMMH_SMEM_BYTES (GSTG*2*HBUF*2)     // 73,728 B -> 2 CTAs/SM

// MODE 0: fp32 C. MODE 2: bias+GELU -> half C. MODE 4: head-split half C.
template<int MODE>
__device__ __forceinline__ void gemm_h_body(const __half* __restrict__ A,
                                            const __half* __restrict__ B,
                                            const float* __restrict__ bias,
                                            void* __restrict__ Cv,
                                            int N, int K, int m0, int n0)
{
    extern __shared__ float gsm[];
    __half* As = (__half*)gsm;               // [2][128][72]
    __half* Bs = As + GSTG*HBUF;

    const int tid  = threadIdx.x;            // 256
    const int warp = tid >> 5;
    const int wm   = warp & 1;
    const int wn   = warp >> 1;

    const unsigned int as_s = (unsigned int)__cvta_generic_to_shared(As);
    const unsigned int bs_s = (unsigned int)__cvta_generic_to_shared(Bs);

    wmma::fragment<wmma::accumulator, 16, 16, 16, float> c[4][2];
    #pragma unroll
    for (int i = 0; i < 4; i++)
        #pragma unroll
        for (int j = 0; j < 2; j++)
            wmma::fill_fragment(c[i][j], 0.0f);

    const int T = K >> 6;

    auto issue = [&](int t) {
        const int k0 = t << 6;
        const unsigned int soff = (unsigned int)((t & 1) * HBUF * 2);
        #pragma unroll
        for (int i = 0; i < 4; i++) {
            int ch   = tid + i * 256;
            int row  = ch >> 3;
            int col8 = (ch & 7) * 8;
            cp_async16(as_s + soff + (unsigned int)((row * HLD + col8) * 2),
                       &A[(size_t)(m0 + row) * K + k0 + col8]);
            cp_async16(bs_s + soff + (unsigned int)((row * HLD + col8) * 2),
                       &B[(size_t)(n0 + row) * K + k0 + col8]);
        }
        cp_commit();
    };

    issue(0);

    for (int t = 0; t < T; t++) {
        cp_wait0();
        __syncthreads();
        if (t + 1 < T) issue(t + 1);     // copy t+1 overlaps compute t

        const int cur = (t & 1) * HBUF;
        #pragma unroll
        for (int kk = 0; kk < 64; kk += 16) {
            wmma::fragment<wmma::matrix_a, 16, 16, 16, __half, wmma::row_major> a[4];
            wmma::fragment<wmma::matrix_b, 16, 16, 16, __half, wmma::col_major> b[2];
            #pragma unroll
            for (int i = 0; i < 4; i++)
                wmma::load_matrix_sync(a[i], &As[cur + (wm * 64 + i * 16) * HLD + kk], HLD);
            #pragma unroll
            for (int j = 0; j < 2; j++)
                wmma::load_matrix_sync(b[j], &Bs[cur + (wn * 32 + j * 16) * HLD + kk], HLD);
            #pragma unroll
            for (int i = 0; i < 4; i++)
                #pragma unroll
                for (int j = 0; j < 2; j++)
                    wmma::mma_sync(c[i][j], a[i], b[j], c[i][j]);
        }
        __syncthreads();
    }

    if (MODE == 2 || MODE == 4) {
        float* stg = gsm;                    // [128][132] (66KB <= 72KB buf? no: 67.6KB < 73.7KB ok)
        #pragma unroll
        for (int i = 0; i < 4; i++)
            #pragma unroll
            for (int j = 0; j < 2; j++)
                wmma::store_matrix_sync(&stg[(wm * 64 + i * 16) * 132 + wn * 32 + j * 16],
                                        c[i][j], 132, wmma::mem_row_major);
        __syncthreads();
        __half* C = (__half*)Cv;
        const int r  = tid >> 1;
        const int c0 = (tid & 1) * 64;
        if (MODE == 2) {
            #pragma unroll
            for (int cc = 0; cc < 64; cc += 4) {
                float4 v = *(float4*)&stg[r * 132 + c0 + cc];
                float4 bb = *(const float4*)&bias[n0 + c0 + cc];
                v.x += bb.x; v.y += bb.y; v.z += bb.z; v.w += bb.w;
                v.x = 0.5f * v.x * (1.0f + erff(v.x * 0.70710678118654752f));
                v.y = 0.5f * v.y * (1.0f + erff(v.y * 0.70710678118654752f));
                v.z = 0.5f * v.z * (1.0f + erff(v.z * 0.70710678118654752f));
                v.w = 0.5f * v.w * (1.0f + erff(v.w * 0.70710678118654752f));
                __half* dst = &C[(size_t)(m0 + r) * N + n0 + c0 + cc];
                *(__half2*)&dst[0] = __floats2half2_rn(v.x, v.y);
                *(__half2*)&dst[2] = __floats2half2_rn(v.z, v.w);
            }
        } else {
            int m = m0 + r;
            int bidx = m >> 11, s = m & 2047;
            int h = (n0 + c0) >> 6;
            __half* dst = &C[(((size_t)(bidx * HH + h)) * SS + s) * DHD];
            #pragma unroll
            for (int cc = 0; cc < 64; cc += 4) {
                float4 v = *(float4*)&stg[r * 132 + c0 + cc];
                *(__half2*)&dst[cc]     = __floats2half2_rn(v.x, v.y);
                *(__half2*)&dst[cc + 2] = __floats2half2_rn(v.z, v.w);
            }
        }
    } else {
        float* C = (float*)Cv;
        #pragma unroll
        for (int i = 0; i < 4; i++) {
            int m = m0 + wm * 64 + i * 16;
            #pragma unroll
            for (int j = 0; j < 2; j++) {
                int n = n0 + wn * 32 + j * 16;
                wmma::store_matrix_sync(C + (size_t)m * N + n, c[i][j], N, wmma::mem_row_major);
            }
        }
    }
}

__global__ void __launch_bounds__(256, 2)
gemm_h(const __half* __restrict__ A, const __half* __restrict__ B,
       float* __restrict__ C, int N, int K)
{
    gemm_h_body<0>(A, B, nullptr, C, N, K, blockIdx.y * 128, blockIdx.x * 128);
}

__global__ void __launch_bounds__(256, 2)
gemm_h_gelu(const __half* __restrict__ A, const __half* __restrict__ B,
            const float* __restrict__ bias, __half* __restrict__ C, int N, int K)
{
    gemm_h_body<2>(A, B, bias, C, N, K, blockIdx.y * 128, blockIdx.x * 128);
}

__global__ void __launch_bounds__(256, 2)
qkv_gemm_h(const __half* __restrict__ X,
           const __half* __restrict__ Wq, const __half* __restrict__ Wk,
           const __half* __restrict__ Wv,
           __half* __restrict__ Qo, __half* __restrict__ Ko, __half* __restrict__ Vo)
{
    const __half* B = (blockIdx.z == 0) ? Wq : (blockIdx.z == 1) ? Wk : Wv;
    __half*       C = (blockIdx.z == 0) ? Qo : (blockIdx.z == 1) ? Ko : Vo;
    gemm_h_body<4>(X, B, nullptr, C, DD, DD, blockIdx.y * 128, blockIdx.x * 128);
}

// ==============  fused flash attention, fp16 MMA, cp.async  ================
#define AT_QH 0
#define AT_KH 18432
#define AT_VH 36864
#define AT_SS 73728
#define AT_ES 141312
#define AT_LS 176128
#define ATT_SMEM_BYTES 176640
#define HLDA 72
#define HBUFA (128*HLDA)

__global__ void __launch_bounds__(512, 1)
attn_fused(const __half* __restrict__ Q, const __half* __restrict__ K,
           const __half* __restrict__ V, float* __restrict__ P,
           __half* __restrict__ AVh)
{
    extern __shared__ char smraw[];
    __half* Qh = (__half*)(smraw + AT_QH);
    __half* Kh = (__half*)(smraw + AT_KH);
    __half* Vh = (__half*)(smraw + AT_VH);
    float*  Ss = (float*)(smraw + AT_SS);
    __half* Es = (__half*)(smraw + AT_ES);
    float*  ls = (float*)(smraw + AT_LS);

    const int bh  = blockIdx.y;
    const int qt  = gridDim.x - 1 - blockIdx.x;
    const int m0  = qt * 128;
    const int tid = threadIdx.x;
    const int warp = tid >> 5;
    const int wm = warp & 3;
    const int wn = warp >> 2;

    const __half* Qb = Q + ((size_t)bh * SS + m0) * DHD;
    const __half* Kb = K + (size_t)bh * SS * DHD;
    const __half* Vb = V + (size_t)bh * SS * DHD;
    float* Pb = P + ((size_t)bh * SS + m0) * SS;

    const unsigned int kh_s = (unsigned int)__cvta_generic_to_shared(Kh);
    const unsigned int vh_s = (unsigned int)__cvta_generic_to_shared(Vh);

    for (int ch = tid; ch < 1024; ch += 512) {
        int r = ch >> 3, c8 = (ch & 7) * 8;
        *(uint4*)&Qh[r * HLDA + c8] = *(const uint4*)&Qb[(size_t)r * DHD + c8];
    }
    if (tid < 128) ls[tid] = 0.0f;

    #pragma unroll
    for (int u = 0; u < 2; u++) {
        int ch = tid + u * 512;
        int r = ch >> 3, c8 = (ch & 7) * 8;
        cp_async16(kh_s + (unsigned int)((r * HLDA + c8) * 2), &Kb[(size_t)r * DHD + c8]);
        cp_async16(vh_s + (unsigned int)((r * HLDA + c8) * 2), &Vb[(size_t)r * DHD + c8]);
    }
    cp_commit();

    wmma::fragment<wmma::accumulator, 16, 16, 16, float> co[2];
    #pragma unroll
    for (int i = 0; i < 2; i++) wmma::fill_fragment(co[i], 0.0f);

    for (int kt = 0; kt <= qt; kt++) {
        const int vcur = (kt & 1) * HBUFA;
        cp_wait0();
        __syncthreads();

        wmma::fragment<wmma::accumulator, 16, 16, 16, float> cs[2][2];
        #pragma unroll
        for (int i = 0; i < 2; i++)
            #pragma unroll
            for (int j = 0; j < 2; j++)
                wmma::fill_fragment(cs[i][j], 0.0f);

        #pragma unroll
        for (int kk = 0; kk < 64; kk += 16) {
            wmma::fragment<wmma::matrix_a, 16, 16, 16, __half, wmma::row_major> a[2];
            wmma::fragment<wmma::matrix_b, 16, 16, 16, __half, wmma::col_major> b[2];
            #pragma unroll
            for (int i = 0; i < 2; i++)
                wmma::load_matrix_sync(a[i], &Qh[(wm * 32 + i * 16) * HLDA + kk], HLDA);
            #pragma unroll
            for (int j = 0; j < 2; j++)
                wmma::load_matrix_sync(b[j], &Kh[(wn * 32 + j * 16) * HLDA + kk], HLDA);
            #pragma unroll
            for (int i = 0; i < 2; i++)
                #pragma unroll
                for (int j = 0; j < 2; j++)
                    wmma::mma_sync(cs[i][j], a[i], b[j], cs[i][j]);
        }
        #pragma unroll
        for (int i = 0; i < 2; i++)
            #pragma unroll
            for (int j = 0; j < 2; j++)
                wmma::store_matrix_sync(&Ss[(wm * 32 + i * 16) * 132 + wn * 32 + j * 16],
                                        cs[i][j], 132, wmma::mem_row_major);
        __syncthreads();

        if (kt < qt) {
            const int k1 = (kt + 1) * 128;
            const unsigned int vdst = vh_s + (unsigned int)((((kt + 1) & 1) * HBUFA) * 2);
            #pragma unroll
            for (int u = 0; u < 2; u++) {
                int ch = tid + u * 512;
                int r = ch >> 3, c8 = (ch & 7) * 8;
                cp_async16(kh_s + (unsigned int)((r * HLDA + c8) * 2),
                           &Kb[(size_t)(k1 + r) * DHD + c8]);
                cp_async16(vdst + (unsigned int)((r * HLDA + c8) * 2),
                           &Vb[(size_t)(k1 + r) * DHD + c8]);
            }
            cp_commit();
        }

        {
            const int k0 = kt * 128;
            int r  = tid >> 2;
            int c0 = (tid & 3) * 32;
            int grow = m0 + r;
            float partial = 0.0f;
            #pragma unroll
            for (int c = 0; c < 32; c += 4) {
                int gc = k0 + c0 + c;
                float4 v = *(float4*)&Ss[r * 132 + c0 + c];
                v.x = (gc + 0 <= grow) ? fexp8(v.x) : 0.0f;
                v.y = (gc + 1 <= grow) ? fexp8(v.y) : 0.0f;
                v.z = (gc + 2 <= grow) ? fexp8(v.z) : 0.0f;
                v.w = (gc + 3 <= grow) ? fexp8(v.w) : 0.0f;
                partial += v.x + v.y + v.z + v.w;
                *(float4*)&Pb[(size_t)r * SS + gc] = v;
                __half* ed = &Es[r * 136 + c0 + c];
                *(__half2*)&ed[0] = __floats2half2_rn(v.x, v.y);
                *(__half2*)&ed[2] = __floats2half2_rn(v.z, v.w);
            }
            atomicAdd(&ls[r], partial);
        }
        __syncthreads();

        #pragma unroll
        for (int kk = 0; kk < 128; kk += 16) {
            wmma::fragment<wmma::matrix_a, 16, 16, 16, __half, wmma::row_major> a[2];
            wmma::fragment<wmma::matrix_b, 16, 16, 16, __half, wmma::row_major> b;
            #pragma unroll
            for (int i = 0; i < 2; i++)
                wmma::load_matrix_sync(a[i], &Es[(wm * 32 + i * 16) * 136 + kk], 136);
            wmma::load_matrix_sync(b, &Vh[vcur + kk * HLDA + wn * 16], HLDA);
            #pragma unroll
            for (int i = 0; i < 2; i++)
                wmma::mma_sync(co[i], a[i], b, co[i]);
        }
        __syncthreads();
    }

    const int zc0 = (qt + 1) * 128;
    if (zc0 < SS) {
        const int rl4 = (SS - zc0) >> 2;
        const float4 z4 = make_float4(0.f, 0.f, 0.f, 0.f);
        for (int i = tid; i < 128 * rl4; i += 512) {
            int r = i / rl4, c4 = (i - r * rl4) * 4;
            st_cs16(&Pb[(size_t)r * SS + zc0 + c4], z4);
        }
    }

    #pragma unroll
    for (int i = 0; i < 2; i++)
        wmma::store_matrix_sync(&Ss[(wm * 32 + i * 16) * 68 + wn * 16],
                                co[i], 68, wmma::mem_row_major);
    __syncthreads();

    const int bi = bh / HH, hi = bh % HH;
    {
        int r  = tid >> 2;
        int c0 = (tid & 3) * 16;
        float inv = 1.0f / ls[r];
        __half* dsth = AVh + ((size_t)bi * SS + m0 + r) * DD + hi * DHD + c0;
        #pragma unroll
        for (int c = 0; c < 16; c += 4) {
            float4 v = *(float4*)&Ss[r * 68 + c0 + c];
            v.x *= inv; v.y *= inv; v.z *= inv; v.w *= inv;
            *(__half2*)&dsth[c]     = __floats2half2_rn(v.x, v.y);
            *(__half2*)&dsth[c + 2] = __floats2half2_rn(v.z, v.w);
        }
    }

    {
        const int rl4 = zc0 >> 2;
        for (int i = tid; i < 128 * rl4; i += 512) {
            int r = i / rl4, c4 = (i - r * rl4) * 4;
            float inv = 1.0f / ls[r];
            float4 v = *(float4*)&Pb[(size_t)r * SS + c4];
            v.x *= inv; v.y *= inv; v.z *= inv; v.w *= inv;
            st_cs16(&Pb[(size_t)r * SS + c4], v);
        }
    }
}

// ---------------- fused residual add (+bias) + LayerNorm (+half copy) ------
__global__ void add_ln(const float* __restrict__ A, const float* __restrict__ Bv,
                       const float* __restrict__ bias,
                       const float* __restrict__ gamma, const float* __restrict__ beta,
                       float* __restrict__ out, __half* __restrict__ outh)
{
    const int row = blockIdx.x;
    const int tid = threadIdx.x;
    __shared__ float buf[DD];
    __shared__ float red[8];

    const float* a  = A  + (size_t)row * DD;
    const float* bp = Bv + (size_t)row * DD;

    float lsum = 0.f;
    #pragma unroll
    for (int i = 0; i < 3; i++) {
        int c = tid + i * 256;
        float v = a[c] + bp[c] + (bias ? bias[c] : 0.0f);
        buf[c] = v;
        lsum += v;
    }
    #pragma unroll
    for (int o = 16; o; o >>= 1) lsum += __shfl_xor_sync(0xffffffffu, lsum, o);
    if ((tid & 31) == 0) red[tid >> 5] = lsum;
    __syncthreads();
    float mu = (red[0]+red[1]+red[2]+red[3]+red[4]+red[5]+red[6]+red[7]) * (1.0f / DD);

    float lvar = 0.f;
    #pragma unroll
    for (int i = 0; i < 3; i++) {
        int c = tid + i * 256;
        float d = buf[c] - mu;
        lvar += d * d;
    }
    #pragma unroll
    for (int o = 16; o; o >>= 1) lvar += __shfl_xor_sync(0xffffffffu, lvar, o);
    __syncthreads();
    if ((tid & 31) == 0) red[tid >> 5] = lvar;
    __syncthreads();
    float var = (red[0]+red[1]+red[2]+red[3]+red[4]+red[5]+red[6]+red[7]) * (1.0f / DD);
    float inv = rsqrtf(var + 1e-5f);

    float* o = out + (size_t)row * DD;
    __half* oh = outh ? outh + (size_t)row * DD : nullptr;
    #pragma unroll
    for (int i = 0; i < 3; i++) {
        int c = tid + i * 256;
        float v = (buf[c] - mu) * inv * gamma[c] + beta[c];
        o[c] = v;
        if (oh) oh[c] = __float2half_rn(v);
    }
}

// ---------------------------------------------------------------------------
extern "C" void kernel_launch(void* const* d_in, const int* in_sizes, int n_in,
                              void* d_out, int out_size)
{
    const float* x   = (const float*)d_in[0];
    const float* Wq  = (const float*)d_in[2];
    const float* Wk  = (const float*)d_in[3];
    const float* Wv  = (const float*)d_in[4];
    const float* Wo  = (const float*)d_in[5];
    const float* bo  = (const float*)d_in[6];
    const float* g1  = (const float*)d_in[7];
    const float* b1  = (const float*)d_in[8];
    const float* W1  = (const float*)d_in[9];
    const float* bb1 = (const float*)d_in[10];
    const float* W2  = (const float*)d_in[11];
    const float* bb2 = (const float*)d_in[12];
    const float* g2  = (const float*)d_in[13];
    const float* b2  = (const float*)d_in[14];

    float* y = (float*)d_out;
    float* P = y + Y_ELEMS;

    float *aop, *hp, *f2p;
    __half *qh, *kh, *vh, *xh, *wqh, *wkh, *wvh, *woh, *w1h, *w2h, *avh, *hh, *f1h;
    cudaGetSymbolAddress((void**)&aop, g_ao);
    cudaGetSymbolAddress((void**)&hp,  g_h);
    cudaGetSymbolAddress((void**)&f2p, g_f2);
    cudaGetSymbolAddress((void**)&qh,  g_qh);
    cudaGetSymbolAddress((void**)&kh,  g_kh);
    cudaGetSymbolAddress((void**)&vh,  g_vh);
    cudaGetSymbolAddress((void**)&xh,  g_xh);
    cudaGetSymbolAddress((void**)&wqh, g_wqh);
    cudaGetSymbolAddress((void**)&wkh, g_wkh);
    cudaGetSymbolAddress((void**)&wvh, g_wvh);
    cudaGetSymbolAddress((void**)&woh, g_woh);
    cudaGetSymbolAddress((void**)&w1h, g_w1h);
    cudaGetSymbolAddress((void**)&w2h, g_w2h);
    cudaGetSymbolAddress((void**)&avh, g_avh);
    cudaGetSymbolAddress((void**)&hh,  g_hh);
    cudaGetSymbolAddress((void**)&f1h, g_f1h);

    cudaFuncSetAttribute(gemm_h, cudaFuncAttributeMaxDynamicSharedMemorySize, GEMMH_SMEM_BYTES);
    cudaFuncSetAttribute(gemm_h_gelu, cudaFuncAttributeMaxDynamicSharedMemorySize, GEMMH_SMEM_BYTES);
    cudaFuncSetAttribute(qkv_gemm_h, cudaFuncAttributeMaxDynamicSharedMemorySize, GEMMH_SMEM_BYTES);
    cudaFuncSetAttribute(attn_fused, cudaFuncAttributeMaxDynamicSharedMemorySize, ATT_SMEM_BYTES);

    // all fp32->fp16 conversions in one launch
    f2h_all<<<F2H_ALL_BLOCKS, 256>>>(x, xh, Wq, wqh, Wk, wkh, Wv, wvh,
                                     Wo, woh, W1, w1h, W2, w2h);

    dim3 g768 (DD  / 128, MM / 128);
    dim3 g3072(DFF / 128, MM / 128);
    dim3 gqkv (DD  / 128, MM / 128, 3);

    // QKV projections (fp16 in, fp16 head-split out)
    qkv_gemm_h<<<gqkv, 256, GEMMH_SMEM_BYTES>>>(xh, wqh, wkh, wvh, qh, kh, vh);

    // fused attention (fp16 MMA) -> P fp32, AV fp16
    attn_fused<<<dim3(SS / 128, BB * HH), 512, ATT_SMEM_BYTES>>>(qh, kh, vh, P, avh);

    // output projection
    gemm_h<<<g768, 256, GEMMH_SMEM_BYTES>>>(avh, woh, aop, DD, DD);

    // h = LN(x + attn_out + bo) -> fp32 + fp16
    add_ln<<<MM, 256>>>(x, aop, bo, g1, b1, hp, hh);

    // FFN1 + bias + GELU fused -> fp16
    gemm_h_gelu<<<g3072, 256, GEMMH_SMEM_BYTES>>>(hh, w1h, bb1, f1h, DFF, DD);

    // FFN2
    gemm_h<<<g768, 256, GEMMH_SMEM_BYTES>>>(f1h, w2h, f2p, DD, DFF);

    // y = LN(h + f + bb2)
    add_ln<<<MM, 256>>>(hp, f2p, bb2, g2, b2, y, nullptr);
}